// round 12
// baseline (speedup 1.0000x reference)
#include <cuda_runtime.h>
#include <cuda_fp16.h>

#define DTC (1.0f/64.0f)
#define VOLR 64.0f
#define NSTEPS 64
#define NK 32
#define NRAYS 16384

// Delta fp16 template: entry (k,z,y,x) = 8 halves (16B):
// {c0,c1}@x, {c2,c3}@x, {dc0,dc1}, {dc2,dc3}  where dc = v@(x+1) - v@x
__device__ uint4 g_templ[NK * 16 * 16 * 16];

__global__ void repack_kernel(const float* __restrict__ t) {
    int idx = blockIdx.x * blockDim.x + threadIdx.x;  // over NK*4096 voxels
    if (idx >= NK * 4096) return;
    int k = idx >> 12;
    int v = idx & 4095;          // z*256 + y*16 + x
    int x = v & 15;
    int x1 = (x < 15) ? 1 : 0;
    const float* src = t + (size_t)k * 4 * 4096 + v;
    __half h[8];
    #pragma unroll
    for (int c = 0; c < 4; c++) {
        float v0 = src[c * 4096];
        float v1 = src[c * 4096 + x1];
        h[c]     = __float2half_rn(v0);
        h[4 + c] = __float2half_rn(v1 - v0);
    }
    g_templ[idx] = *reinterpret_cast<uint4*>(h);
}

__device__ __forceinline__ float warp_sum(float v) {
    #pragma unroll
    for (int off = 16; off; off >>= 1)
        v += __shfl_xor_sync(0xffffffffu, v, off);
    return v;
}

#define H2(u) (*reinterpret_cast<const __half2*>(&(u)))

__global__ void __launch_bounds__(128) raymarch_kernel(
    const float* __restrict__ raypos, const float* __restrict__ raydir,
    const float* __restrict__ tminmax, const float* __restrict__ primpos,
    const float* __restrict__ primrot, const float* __restrict__ primscale,
    float* __restrict__ out)
{
    const int lane = threadIdx.x & 31;
    const int ray  = blockIdx.x * 4 + (threadIdx.x >> 5);
    const unsigned FULL = 0xffffffffu;

    // lane k handles primitive k (K == 32 == warp width)
    const int k = lane;
    const float px = primpos[k*3+0], py = primpos[k*3+1], pz = primpos[k*3+2];
    const float r00 = primrot[k*9+0], r01 = primrot[k*9+1], r02 = primrot[k*9+2];
    const float r10 = primrot[k*9+3], r11 = primrot[k*9+4], r12 = primrot[k*9+5];
    const float r20 = primrot[k*9+6], r21 = primrot[k*9+7], r22 = primrot[k*9+8];
    const float s0 = primscale[k*3+0], s1 = primscale[k*3+1], s2 = primscale[k*3+2];

    const float rpx = raypos[ray*3+0], rpy = raypos[ray*3+1], rpz = raypos[ray*3+2];
    const float rdx = raydir[ray*3+0], rdy = raydir[ray*3+1], rdz = raydir[ray*3+2];
    const float tmin = tminmax[ray*2+0], tmax = tminmax[ray*2+1];

    // Grid-space affine: g(t) = Bg + t*Dg, inside <=> all axes in [0,15]
    const float wx = rpx - px, wy = rpy - py, wz = rpz - pz;
    const float Bz = fmaf(s0 * fmaf(r00, wx, fmaf(r01, wy, r02 * wz)), 7.5f, 7.5f);
    const float By = fmaf(s1 * fmaf(r10, wx, fmaf(r11, wy, r12 * wz)), 7.5f, 7.5f);
    const float Bx = fmaf(s2 * fmaf(r20, wx, fmaf(r21, wy, r22 * wz)), 7.5f, 7.5f);
    const float Dz = 7.5f * (s0 * fmaf(r00, rdx, fmaf(r01, rdy, r02 * rdz)));
    const float Dy = 7.5f * (s1 * fmaf(r10, rdx, fmaf(r11, rdy, r12 * rdz)));
    const float Dx = 7.5f * (s2 * fmaf(r20, rdx, fmaf(r21, rdy, r22 * rdz)));

    // Per-lane slab interval in t for g in [0,15] (conservative, widened 1 step)
    float ta = -1e30f, tb = 1e30f;
    {
        const float BB[3] = {Bz, By, Bx};
        const float DD[3] = {Dz, Dy, Dx};
        #pragma unroll
        for (int a = 0; a < 3; a++) {
            float B = BB[a], D = DD[a];
            if (fabsf(D) < 1e-9f) {
                if (B < 0.f || B > 15.f) { ta = 1e30f; tb = -1e30f; }
            } else {
                float inv = 1.0f / D;
                float t0 = (0.f  - B) * inv;
                float t1 = (15.f - B) * inv;
                float lo = fminf(t0, t1), hi = fmaxf(t0, t1);
                ta = fmaxf(ta, lo); tb = fminf(tb, hi);
            }
        }
    }
    int ia, ib;
    if (ta > tb) { ia = NSTEPS; ib = -1; }
    else {
        float iaf = floorf((ta - tmin) * VOLR) - 1.0f;
        float ibf = ceilf((tb - tmin) * VOLR) + 1.0f;
        ia = (int)fminf(fmaxf(iaf, 0.0f), (float)NSTEPS);
        ib = (int)fminf(fmaxf(ibf, -1.0f), (float)(NSTEPS - 1));
    }
    int i_start = ia, i_end = ib;
    #pragma unroll
    for (int off = 16; off; off >>= 1) {
        i_start = min(i_start, __shfl_xor_sync(FULL, i_start, off));
        i_end   = max(i_end,   __shfl_xor_sync(FULL, i_end,   off));
    }

    // Uniform step limit from tmax: i valid iff fmaf(i,DTC,tmin) < tmax (exact fixup)
    int ilim = (int)ceilf((tmax - tmin) * VOLR);
    ilim = max(0, min(ilim, NSTEPS));
    while (ilim > 0 && fmaf((float)(ilim - 1), DTC, tmin) >= tmax) ilim--;
    while (ilim < NSTEPS && fmaf((float)ilim, DTC, tmin) < tmax) ilim++;
    i_end = min(i_end, ilim - 1);

    const uint4* __restrict__ tk = g_templ + (k << 12);

    float acc0 = 0.f, acc1 = 0.f, acc2 = 0.f;   // per-lane deferred rgb accum
    float alpha = 0.f;                           // identical across lanes

    // Pipeline state buffers (2-stage)
    uint4 E0a, E0b, E0c, E0d, E1a, E1b, E1c, E1d;
    float fzA, fzB;
    __half2 fxA, fyA, fxB, fyB;
    const uint4 Z4 = make_uint4(0u, 0u, 0u, 0u);

    // Issue stage: compute coords for step I, launch predicated loads into buffer.
    #define ISSUE(I, Ea, Eb, Ec, Ed, FZ, FX2, FY2)                               \
    {                                                                            \
        float t_ = fmaf((float)(I), DTC, tmin);                                  \
        float gz_ = fmaf(t_, Dz, Bz), gy_ = fmaf(t_, Dy, By), gx_ = fmaf(t_, Dx, Bx); \
        bool in_ = fminf(fminf(gz_, gy_), gx_) >= 0.f &&                         \
                   fmaxf(fmaxf(gz_, gy_), gx_) <= 15.f;                          \
        float izf_ = fminf(fmaxf(floorf(gz_), 0.f), 14.f);                       \
        float iyf_ = fminf(fmaxf(floorf(gy_), 0.f), 14.f);                       \
        float ixf_ = fminf(fmaxf(floorf(gx_), 0.f), 14.f);                       \
        FZ  = gz_ - izf_;                                                        \
        FX2 = __float2half2_rn(gx_ - ixf_);                                      \
        FY2 = __float2half2_rn(gy_ - iyf_);                                      \
        const uint4* p_ = tk + (((int)izf_) << 8) + (((int)iyf_) << 4) + (int)ixf_; \
        Ea = in_ ? __ldg(p_)       : Z4;                                         \
        Eb = in_ ? __ldg(p_ + 16)  : Z4;                                         \
        Ec = in_ ? __ldg(p_ + 256) : Z4;                                         \
        Ed = in_ ? __ldg(p_ + 272) : Z4;                                         \
    }

    // Process stage: lerp buffer -> v0..v3, then composite (alpha warp-summed).
    #define PROCESS(Ea, Eb, Ec, Ed, FZ, FX2, FY2)                                \
    {                                                                            \
        __half2 a00 = __hfma2(FX2, H2((Ea).z), H2((Ea).x));                      \
        __half2 b00 = __hfma2(FX2, H2((Ea).w), H2((Ea).y));                      \
        __half2 a01 = __hfma2(FX2, H2((Eb).z), H2((Eb).x));                      \
        __half2 b01 = __hfma2(FX2, H2((Eb).w), H2((Eb).y));                      \
        __half2 a10 = __hfma2(FX2, H2((Ec).z), H2((Ec).x));                      \
        __half2 b10 = __hfma2(FX2, H2((Ec).w), H2((Ec).y));                      \
        __half2 a11 = __hfma2(FX2, H2((Ed).z), H2((Ed).x));                      \
        __half2 b11 = __hfma2(FX2, H2((Ed).w), H2((Ed).y));                      \
        __half2 z0a = __hfma2(FY2, __hsub2(a01, a00), a00);                      \
        __half2 z0b = __hfma2(FY2, __hsub2(b01, b00), b00);                      \
        __half2 z1a = __hfma2(FY2, __hsub2(a11, a10), a10);                      \
        __half2 z1b = __hfma2(FY2, __hsub2(b11, b10), b10);                      \
        float2 f0a = __half22float2(z0a), f0b = __half22float2(z0b);             \
        float2 f1a = __half22float2(z1a), f1b = __half22float2(z1b);             \
        float v0 = fmaf(FZ, f1a.x - f0a.x, f0a.x);                               \
        float v1 = fmaf(FZ, f1a.y - f0a.y, f0a.y);                               \
        float v2 = fmaf(FZ, f1b.x - f0b.x, f0b.x);                               \
        float v3 = fmaf(FZ, f1b.y - f0b.y, f0b.y);                               \
        float sa = warp_sum(v3);                                                 \
        float na = fminf(fmaf(sa, DTC, alpha), 1.0f);                            \
        float contrib = na - alpha;                                              \
        acc0 = fmaf(v0, contrib, acc0);                                          \
        acc1 = fmaf(v1, contrib, acc1);                                          \
        acc2 = fmaf(v2, contrib, acc2);                                          \
        alpha = na;                                                              \
    }

    int i = i_start;
    if (i <= i_end) {
        ISSUE(i, E0a, E0b, E0c, E0d, fzA, fxA, fyA);
        while (true) {
            if (i + 1 <= i_end) ISSUE(i + 1, E1a, E1b, E1c, E1d, fzB, fxB, fyB);
            PROCESS(E0a, E0b, E0c, E0d, fzA, fxA, fyA);
            if (alpha >= 1.0f) break;          // uniform; rest are exact no-ops
            i++;
            if (i > i_end) break;
            if (i + 1 <= i_end) ISSUE(i + 1, E0a, E0b, E0c, E0d, fzA, fxA, fyA);
            PROCESS(E1a, E1b, E1c, E1d, fzB, fxB, fyB);
            if (alpha >= 1.0f) break;
            i++;
            if (i > i_end) break;
        }
    }

    // one-time rgb reduction over primitives (lanes)
    float r0 = warp_sum(acc0);
    float r1 = warp_sum(acc1);
    float r2 = warp_sum(acc2);

    // planes: [0..2]=rgb, [3]=alpha, [4..6]=rgb, [7]=alpha
    if (lane == 0) {
        out[0 * NRAYS + ray] = r0;
        out[1 * NRAYS + ray] = r1;
        out[2 * NRAYS + ray] = r2;
        out[3 * NRAYS + ray] = alpha;
        out[4 * NRAYS + ray] = r0;
        out[5 * NRAYS + ray] = r1;
        out[6 * NRAYS + ray] = r2;
        out[7 * NRAYS + ray] = alpha;
    }
}

extern "C" void kernel_launch(void* const* d_in, const int* in_sizes, int n_in,
                              void* d_out, int out_size) {
    const float* raypos    = (const float*)d_in[0];
    const float* raydir    = (const float*)d_in[1];
    const float* tminmax   = (const float*)d_in[2];
    const float* primpos   = (const float*)d_in[3];
    const float* primrot   = (const float*)d_in[4];
    const float* primscale = (const float*)d_in[5];
    const float* templ     = (const float*)d_in[6];
    float* out = (float*)d_out;

    repack_kernel<<<(NK * 4096 + 255) / 256, 256>>>(templ);
    raymarch_kernel<<<NRAYS / 4, 128>>>(raypos, raydir, tminmax,
                                        primpos, primrot, primscale, out);
}